// round 3
// baseline (speedup 1.0000x reference)
#include <cuda_runtime.h>
#include <cuda_bf16.h>
#include <cstdint>
#include <math.h>

#define BB 128
#define TT 1024
#define HH 512
#define LL 2

// ---------------- scratch (device globals; no allocation allowed) ----------------
__device__ float g_attn_applied[BB * HH];
__device__ float g_wpacked[HH * HH];        // comb_w columns 1..512, contiguous
__device__ float g_x0[BB * HH];
__device__ float g_x1[BB * HH];
__device__ float g_x2[BB * HH];
__device__ float g_gx[BB * 3 * HH];
__device__ float g_gh[BB * 3 * HH];

// =====================================================================
// K1: fused attention — single pass over encoder_outputs (online softmax)
// grid = 128 (one CTA per batch), block = 512 (16 warps)
// =====================================================================
__global__ __launch_bounds__(512) void attn_kernel(
    const float* __restrict__ hidden,
    const float* __restrict__ enc,
    const float* __restrict__ attn_w,
    const float* __restrict__ attn_b,
    float* __restrict__ out_weights)   // d_out + 128 + L*B*H  (B x T)
{
    const int b    = blockIdx.x;
    const int tid  = threadIdx.x;
    const int w    = tid >> 5;
    const int lane = tid & 31;

    __shared__ float sh_scores[TT];          // 4 KB
    __shared__ float sh_slab[16 * HH];       // 32 KB
    __shared__ float sh_m[16], sh_z[16];
    __shared__ float sh_red[16];
    __shared__ float sh_hid;

    // ---- hid_dot = hidden_attn[b] . w_h  (+ bias) ----
    float part = hidden[b * HH + tid]        * attn_w[tid]
               + hidden[(BB + b) * HH + tid] * attn_w[HH + tid];
    #pragma unroll
    for (int o = 16; o > 0; o >>= 1) part += __shfl_xor_sync(0xffffffffu, part, o);
    if (lane == 0) sh_red[w] = part;
    __syncthreads();
    if (tid == 0) {
        float s = 0.f;
        #pragma unroll
        for (int i = 0; i < 16; i++) s += sh_red[i];
        sh_hid = s + attn_b[0];
    }
    __syncthreads();
    const float base = sh_hid;

    // ---- w_e into registers (lane-distributed: h = 4*lane + 128*c + j) ----
    const float4* we4 = (const float4*)(attn_w + LL * HH);
    float we[16];
    #pragma unroll
    for (int c = 0; c < 4; c++) ((float4*)we)[c] = we4[lane + c * 32];

    float m = -INFINITY, Z = 0.f;
    float acc[16];
    #pragma unroll
    for (int i = 0; i < 16; i++) acc[i] = 0.f;

    const float4* encb = (const float4*)(enc + (size_t)b * TT * HH);

    // software-pipelined loop over this warp's 64 rows (t = w, w+16, ...)
    float ev[16], nv[16];
    int t = w;
    #pragma unroll
    for (int c = 0; c < 4; c++) ((float4*)nv)[c] = encb[(size_t)t * 128 + lane + c * 32];

    for (int it = 0; it < TT / 16; ++it) {
        #pragma unroll
        for (int i = 0; i < 16; i++) ev[i] = nv[i];
        const int tn = t + 16;
        if (it + 1 < TT / 16) {
            #pragma unroll
            for (int c = 0; c < 4; c++) ((float4*)nv)[c] = encb[(size_t)tn * 128 + lane + c * 32];
        }
        // score dot
        float s = 0.f;
        #pragma unroll
        for (int i = 0; i < 16; i++) s = fmaf(ev[i], we[i], s);
        #pragma unroll
        for (int o = 16; o > 0; o >>= 1) s += __shfl_xor_sync(0xffffffffu, s, o);
        s += base;
        if (lane == 0) sh_scores[t] = s;

        // online softmax update
        const float mn = fmaxf(m, s);
        const float sc = __expf(m - mn);
        const float p  = __expf(s - mn);
        Z = Z * sc + p;
        #pragma unroll
        for (int i = 0; i < 16; i++) acc[i] = fmaf(p, ev[i], acc[i] * sc);
        m = mn;
        t = tn;
    }

    sh_m[w] = m; sh_z[w] = Z;
    __syncthreads();

    float M = sh_m[0];
    #pragma unroll
    for (int i = 1; i < 16; i++) M = fmaxf(M, sh_m[i]);
    float Zt = 0.f;
    #pragma unroll
    for (int i = 0; i < 16; i++) Zt += sh_z[i] * __expf(sh_m[i] - M);

    const float myscale = __expf(m - M);
    float4* slab4 = (float4*)(sh_slab + w * HH);
    #pragma unroll
    for (int c = 0; c < 4; c++) {
        float4 a = ((float4*)acc)[c];
        a.x *= myscale; a.y *= myscale; a.z *= myscale; a.w *= myscale;
        slab4[c * 32 + lane] = a;
    }
    __syncthreads();

    // column sum across 16 warps -> attn_applied
    float v = 0.f;
    #pragma unroll
    for (int i = 0; i < 16; i++) v += sh_slab[i * HH + tid];
    const float invZ = 1.f / Zt;
    g_attn_applied[b * HH + tid] = v * invZ;

    // attn_weights output
    for (int tt = tid; tt < TT; tt += 512)
        out_weights[(size_t)b * TT + tt] = __expf(sh_scores[tt] - M) * invZ;
}

// =====================================================================
// Generic fp32 tile GEMM: C[m,n] = sum_k A[m,k]*B[n,k]  (both K-major)
// CTA tile 32x64, blockDim 128, thread tile 4x4, K multiple of 32
// =====================================================================
__device__ __forceinline__ void gemm_tile(
    const float* __restrict__ A, const float* __restrict__ Bm, float* __restrict__ C,
    int K, int Ncols, int m0, int n0,
    const float* __restrict__ bias,
    const float* __restrict__ u, int ustride,
    const float* __restrict__ v, int vstride,
    int relu, float* shA, float* shB)
{
    const int tid = threadIdx.x;
    const int tn = tid & 15, tm = tid >> 4;     // tn 0..15, tm 0..7
    const int r = tid >> 3, c4 = tid & 7;       // load mapping
    float acc[4][4];
    #pragma unroll
    for (int i = 0; i < 4; i++)
        #pragma unroll
        for (int j = 0; j < 4; j++) acc[i][j] = 0.f;

    for (int k0 = 0; k0 < K; k0 += 32) {
        // A tile 32x32 -> shA[m][k] (stride 32)
        #pragma unroll
        for (int rr = r; rr < 32; rr += 16) {
            float4 av = *(const float4*)&A[(size_t)(m0 + rr) * K + k0 + c4 * 4];
            *(float4*)&shA[rr * 32 + c4 * 4] = av;
        }
        // B tile 64x32 -> shB[k][n] (stride 68, 16B-aligned rows)
        #pragma unroll
        for (int rr = r; rr < 64; rr += 16) {
            float4 bv = *(const float4*)&Bm[(size_t)(n0 + rr) * K + k0 + c4 * 4];
            shB[(c4 * 4 + 0) * 68 + rr] = bv.x;
            shB[(c4 * 4 + 1) * 68 + rr] = bv.y;
            shB[(c4 * 4 + 2) * 68 + rr] = bv.z;
            shB[(c4 * 4 + 3) * 68 + rr] = bv.w;
        }
        __syncthreads();
        #pragma unroll
        for (int k = 0; k < 32; k++) {
            const float a0 = shA[(tm * 4 + 0) * 32 + k];
            const float a1 = shA[(tm * 4 + 1) * 32 + k];
            const float a2 = shA[(tm * 4 + 2) * 32 + k];
            const float a3 = shA[(tm * 4 + 3) * 32 + k];
            const float4 b4 = *(const float4*)&shB[k * 68 + tn * 4];
            acc[0][0] = fmaf(a0, b4.x, acc[0][0]); acc[0][1] = fmaf(a0, b4.y, acc[0][1]);
            acc[0][2] = fmaf(a0, b4.z, acc[0][2]); acc[0][3] = fmaf(a0, b4.w, acc[0][3]);
            acc[1][0] = fmaf(a1, b4.x, acc[1][0]); acc[1][1] = fmaf(a1, b4.y, acc[1][1]);
            acc[1][2] = fmaf(a1, b4.z, acc[1][2]); acc[1][3] = fmaf(a1, b4.w, acc[1][3]);
            acc[2][0] = fmaf(a2, b4.x, acc[2][0]); acc[2][1] = fmaf(a2, b4.y, acc[2][1]);
            acc[2][2] = fmaf(a2, b4.z, acc[2][2]); acc[2][3] = fmaf(a2, b4.w, acc[2][3]);
            acc[3][0] = fmaf(a3, b4.x, acc[3][0]); acc[3][1] = fmaf(a3, b4.y, acc[3][1]);
            acc[3][2] = fmaf(a3, b4.z, acc[3][2]); acc[3][3] = fmaf(a3, b4.w, acc[3][3]);
        }
        __syncthreads();
    }
    #pragma unroll
    for (int i = 0; i < 4; i++) {
        const int m = m0 + tm * 4 + i;
        const float uu = u ? u[(size_t)m * ustride] : 0.f;
        #pragma unroll
        for (int j = 0; j < 4; j++) {
            const int n = n0 + tn * 4 + j;
            float cv = acc[i][j];
            if (bias) cv += bias[n];
            if (u)    cv = fmaf(uu, v[(size_t)n * vstride], cv);
            if (relu) cv = fmaxf(cv, 0.f);
            C[(size_t)m * Ncols + n] = cv;
        }
    }
}

// repack comb_w[:,1:513] -> contiguous 512x512
__global__ void repack_kernel(const float* __restrict__ comb_w) {
    const int i = blockIdx.x * blockDim.x + threadIdx.x;
    if (i < HH * HH) {
        const int h = i >> 9, j = i & 511;
        g_wpacked[i] = comb_w[h * 513 + 1 + j];
    }
}

// comb: x0 = relu(attn_applied @ wpacked^T + comb_b + input0*comb_w[:,0])
// grid (8,4), block 128
__global__ __launch_bounds__(128) void comb_gemm_kernel(
    const float* __restrict__ input, const float* __restrict__ comb_w,
    const float* __restrict__ comb_b)
{
    __shared__ float shA[32 * 32];
    __shared__ float shB[32 * 68];
    gemm_tile(g_attn_applied, g_wpacked, g_x0, HH, HH,
              blockIdx.y * 32, blockIdx.x * 64,
              comb_b, input + 7, 8, comb_w, 513, 1, shA, shB);
}

// GRU layer GEMMs: gx = x @ Wih^T + bih ; gh = hid @ Whh^T + bhh
// grid (48,4), block 128  (nt<24 -> gx, else gh)
__global__ __launch_bounds__(128) void gru_gemm_kernel(
    int layer,
    const float* __restrict__ hid,
    const float* __restrict__ wih, const float* __restrict__ whh,
    const float* __restrict__ bih, const float* __restrict__ bhh)
{
    __shared__ float shA[32 * 32];
    __shared__ float shB[32 * 68];
    const int nt = blockIdx.x;
    const int m0 = blockIdx.y * 32;
    const float* x = (layer == 0) ? g_x0 : g_x1;
    if (nt < 24)
        gemm_tile(x,   wih, g_gx, HH, 3 * HH, m0, nt * 64,        bih, nullptr, 0, nullptr, 0, 0, shA, shB);
    else
        gemm_tile(hid, whh, g_gh, HH, 3 * HH, m0, (nt - 24) * 64, bhh, nullptr, 0, nullptr, 0, 0, shA, shB);
}

// GRU gates: h_new = (1-z)*n + z*h_prev ; write to d_out hidden + next-x scratch
__global__ void gate_kernel(int layer, const float* __restrict__ hprev,
                            float* __restrict__ hout)
{
    const int i = blockIdx.x * blockDim.x + threadIdx.x;
    if (i >= BB * HH) return;
    const int b = i >> 9, h = i & 511;
    const float* gxb = g_gx + (size_t)b * 3 * HH;
    const float* ghb = g_gh + (size_t)b * 3 * HH;
    const float r = 1.f / (1.f + __expf(-(gxb[h]        + ghb[h])));
    const float z = 1.f / (1.f + __expf(-(gxb[h + 512]  + ghb[h + 512])));
    const float n = tanhf(gxb[h + 1024] + r * ghb[h + 1024]);
    const float hp = hprev[i];
    const float hn = (1.f - z) * n + z * hp;
    hout[i] = hn;
    float* xnext = (layer == 0) ? g_x1 : g_x2;
    xnext[i] = hn;
}

// output GEMV: out[b] = x2[b,:] . out_w + out_b
__global__ void out_kernel(const float* __restrict__ out_w,
                           const float* __restrict__ out_b,
                           float* __restrict__ out)
{
    const int b = blockIdx.x;
    const int tid = threadIdx.x;   // 128
    float s = 0.f;
    #pragma unroll
    for (int j = tid; j < HH; j += 128) s = fmaf(g_x2[b * HH + j], out_w[j], s);
    #pragma unroll
    for (int o = 16; o > 0; o >>= 1) s += __shfl_xor_sync(0xffffffffu, s, o);
    __shared__ float red[4];
    if ((tid & 31) == 0) red[tid >> 5] = s;
    __syncthreads();
    if (tid == 0) out[b] = red[0] + red[1] + red[2] + red[3] + out_b[0];
}

// =====================================================================
extern "C" void kernel_launch(void* const* d_in, const int* in_sizes, int n_in,
                              void* d_out, int out_size)
{
    const float* input   = (const float*)d_in[0];   // (128, 8)
    const float* hidden  = (const float*)d_in[1];   // (2, 128, 512)
    const float* enc     = (const float*)d_in[2];   // (128, 1024, 512)
    const float* attn_w  = (const float*)d_in[3];   // (1, 1536)
    const float* attn_b  = (const float*)d_in[4];   // (1,)
    const float* comb_w  = (const float*)d_in[5];   // (512, 513)
    const float* comb_b  = (const float*)d_in[6];   // (512,)
    const float* gwih    = (const float*)d_in[7];   // (2, 1536, 512)
    const float* gwhh    = (const float*)d_in[8];   // (2, 1536, 512)
    const float* gbih    = (const float*)d_in[9];   // (2, 1536)
    const float* gbhh    = (const float*)d_in[10];  // (2, 1536)
    const float* out_w   = (const float*)d_in[11];  // (1, 512)
    const float* out_b   = (const float*)d_in[12];  // (1,)

    float* out        = (float*)d_out;              // (128,)
    float* out_hidden = out + BB;                   // (2,128,512)
    float* out_attnw  = out + BB + LL * BB * HH;    // (128,1024)

    repack_kernel<<<512, 512>>>(comb_w);
    attn_kernel<<<BB, 512>>>(hidden, enc, attn_w, attn_b, out_attnw);
    comb_gemm_kernel<<<dim3(8, 4), 128>>>(input, comb_w, comb_b);

    // layer 0
    gru_gemm_kernel<<<dim3(48, 4), 128>>>(0, hidden, gwih, gwhh, gbih, gbhh);
    gate_kernel<<<256, 256>>>(0, hidden, out_hidden);
    // layer 1
    gru_gemm_kernel<<<dim3(48, 4), 128>>>(1, hidden + BB * HH,
                                          gwih + 3 * HH * HH, gwhh + 3 * HH * HH,
                                          gbih + 3 * HH, gbhh + 3 * HH);
    gate_kernel<<<256, 256>>>(1, hidden + BB * HH, out_hidden + BB * HH);

    out_kernel<<<BB, 128>>>(out_w, out_b, out);
}

// round 4
// speedup vs baseline: 1.7469x; 1.7469x over previous
#include <cuda_runtime.h>
#include <cuda_bf16.h>
#include <cstdint>
#include <math.h>

#define BB 128
#define TT 1024
#define HH 512
#define LL 2

// ---------------- scratch (device globals; no allocation allowed) ----------------
__device__ float g_attn_applied[BB * HH];
__device__ float g_wpacked[HH * HH];            // comb_w columns 1..512, contiguous
__device__ float g_x0[BB * HH];                 // comb output (relu)
__device__ float g_x1[BB * HH];                 // layer0 hidden out
__device__ float g_x2[BB * HH];                 // layer1 hidden out
__device__ float g_gh[2 * BB * 3 * HH];         // gh for both layers (bias included)
__device__ float g_gxp[2 * BB * 3 * HH];        // gx split-K partials (2 halves)
__device__ float g_combp[4 * BB * HH];          // comb split-K partials (4 quarters)

// =====================================================================
// K1: fused attention — single pass over encoder_outputs (online softmax)
// grid = 128 (one CTA per batch), block = 512 (16 warps)
// =====================================================================
__global__ __launch_bounds__(512) void attn_kernel(
    const float* __restrict__ hidden,
    const float* __restrict__ enc,
    const float* __restrict__ attn_w,
    const float* __restrict__ attn_b,
    float* __restrict__ out_weights)
{
    const int b    = blockIdx.x;
    const int tid  = threadIdx.x;
    const int w    = tid >> 5;
    const int lane = tid & 31;

    __shared__ float sh_scores[TT];
    __shared__ float sh_slab[16 * HH];
    __shared__ float sh_m[16], sh_z[16];
    __shared__ float sh_red[16];
    __shared__ float sh_hid;

    // hid_dot = hidden_attn[b] . w_h (+ bias)
    float part = hidden[b * HH + tid]        * attn_w[tid]
               + hidden[(BB + b) * HH + tid] * attn_w[HH + tid];
    #pragma unroll
    for (int o = 16; o > 0; o >>= 1) part += __shfl_xor_sync(0xffffffffu, part, o);
    if (lane == 0) sh_red[w] = part;
    __syncthreads();
    if (tid == 0) {
        float s = 0.f;
        #pragma unroll
        for (int i = 0; i < 16; i++) s += sh_red[i];
        sh_hid = s + attn_b[0];
    }
    __syncthreads();
    const float base = sh_hid;

    const float4* we4 = (const float4*)(attn_w + LL * HH);
    float we[16];
    #pragma unroll
    for (int c = 0; c < 4; c++) ((float4*)we)[c] = we4[lane + c * 32];

    float m = -INFINITY, Z = 0.f;
    float acc[16];
    #pragma unroll
    for (int i = 0; i < 16; i++) acc[i] = 0.f;

    const float4* encb = (const float4*)(enc + (size_t)b * TT * HH);

    float ev[16], nv[16];
    int t = w;
    #pragma unroll
    for (int c = 0; c < 4; c++) ((float4*)nv)[c] = encb[(size_t)t * 128 + lane + c * 32];

    for (int it = 0; it < TT / 16; ++it) {
        #pragma unroll
        for (int i = 0; i < 16; i++) ev[i] = nv[i];
        const int tn = t + 16;
        if (it + 1 < TT / 16) {
            #pragma unroll
            for (int c = 0; c < 4; c++) ((float4*)nv)[c] = encb[(size_t)tn * 128 + lane + c * 32];
        }
        float s = 0.f;
        #pragma unroll
        for (int i = 0; i < 16; i++) s = fmaf(ev[i], we[i], s);
        #pragma unroll
        for (int o = 16; o > 0; o >>= 1) s += __shfl_xor_sync(0xffffffffu, s, o);
        s += base;
        if (lane == 0) sh_scores[t] = s;

        const float mn = fmaxf(m, s);
        const float sc = __expf(m - mn);
        const float p  = __expf(s - mn);
        Z = Z * sc + p;
        #pragma unroll
        for (int i = 0; i < 16; i++) acc[i] = fmaf(p, ev[i], acc[i] * sc);
        m = mn;
        t = tn;
    }

    sh_m[w] = m; sh_z[w] = Z;
    __syncthreads();

    float M = sh_m[0];
    #pragma unroll
    for (int i = 1; i < 16; i++) M = fmaxf(M, sh_m[i]);
    float Zt = 0.f;
    #pragma unroll
    for (int i = 0; i < 16; i++) Zt += sh_z[i] * __expf(sh_m[i] - M);

    const float myscale = __expf(m - M);
    float4* slab4 = (float4*)(sh_slab + w * HH);
    #pragma unroll
    for (int c = 0; c < 4; c++) {
        float4 a = ((float4*)acc)[c];
        a.x *= myscale; a.y *= myscale; a.z *= myscale; a.w *= myscale;
        slab4[c * 32 + lane] = a;
    }
    __syncthreads();

    float v = 0.f;
    #pragma unroll
    for (int i = 0; i < 16; i++) v += sh_slab[i * HH + tid];
    const float invZ = 1.f / Zt;
    g_attn_applied[b * HH + tid] = v * invZ;

    for (int tt = tid; tt < TT; tt += 512)
        out_weights[(size_t)b * TT + tt] = __expf(sh_scores[tt] - M) * invZ;
}

// =====================================================================
// Double-buffered fp32 GEMM tile: C[m,n] (+=bias) = sum_k A[m,k]*B[n,k]
// CTA tile 32x64, 128 threads, thread tile 4x4, K-chunk 32, ldA=ldB=512
// =====================================================================
__device__ __forceinline__ void gemm_db(
    const float* __restrict__ A, const float* __restrict__ B, float* __restrict__ C,
    int Ncols, int m0, int n0, int k0, int klen,
    const float* __restrict__ bias, float* shA, float* shB)
{
    const int tid = threadIdx.x;
    const int tm = (tid >> 4) * 4;      // 0..28
    const int tn = (tid & 15) * 4;      // 0..60
    const int rA = tid >> 2;            // 0..31  (A copy row)
    const int sA = (tid & 3) * 8;       // k offset within chunk
    const int rB = tid >> 3;            // 0..15  (B copy base row)
    const int cB = (tid & 7) * 4;       // k offset within chunk

    const float* Ag = A + (size_t)(m0 + rA) * HH + k0 + sA;
    const float* Bg = B + (size_t)(n0 + rB) * HH + k0 + cB;

    float4 pa0, pa1, pb0, pb1, pb2, pb3;
    pa0 = *(const float4*)(Ag);
    pa1 = *(const float4*)(Ag + 4);
    pb0 = *(const float4*)(Bg);
    pb1 = *(const float4*)(Bg + (size_t)16 * HH);
    pb2 = *(const float4*)(Bg + (size_t)32 * HH);
    pb3 = *(const float4*)(Bg + (size_t)48 * HH);

    float acc[4][4];
    #pragma unroll
    for (int i = 0; i < 4; i++)
        #pragma unroll
        for (int j = 0; j < 4; j++) acc[i][j] = 0.f;

    const int nk = klen >> 5;

    // stage chunk 0
    *(float4*)&shA[rA * 32 + sA]     = pa0;
    *(float4*)&shA[rA * 32 + sA + 4] = pa1;
    {
        shB[(cB + 0) * 68 + rB] = pb0.x; shB[(cB + 1) * 68 + rB] = pb0.y;
        shB[(cB + 2) * 68 + rB] = pb0.z; shB[(cB + 3) * 68 + rB] = pb0.w;
        shB[(cB + 0) * 68 + rB + 16] = pb1.x; shB[(cB + 1) * 68 + rB + 16] = pb1.y;
        shB[(cB + 2) * 68 + rB + 16] = pb1.z; shB[(cB + 3) * 68 + rB + 16] = pb1.w;
        shB[(cB + 0) * 68 + rB + 32] = pb2.x; shB[(cB + 1) * 68 + rB + 32] = pb2.y;
        shB[(cB + 2) * 68 + rB + 32] = pb2.z; shB[(cB + 3) * 68 + rB + 32] = pb2.w;
        shB[(cB + 0) * 68 + rB + 48] = pb3.x; shB[(cB + 1) * 68 + rB + 48] = pb3.y;
        shB[(cB + 2) * 68 + rB + 48] = pb3.z; shB[(cB + 3) * 68 + rB + 48] = pb3.w;
    }
    __syncthreads();

    int buf = 0;
    for (int c = 0; c < nk; ++c) {
        if (c + 1 < nk) {
            const float* Ag2 = Ag + (c + 1) * 32;
            const float* Bg2 = Bg + (c + 1) * 32;
            pa0 = *(const float4*)(Ag2);
            pa1 = *(const float4*)(Ag2 + 4);
            pb0 = *(const float4*)(Bg2);
            pb1 = *(const float4*)(Bg2 + (size_t)16 * HH);
            pb2 = *(const float4*)(Bg2 + (size_t)32 * HH);
            pb3 = *(const float4*)(Bg2 + (size_t)48 * HH);
        }
        const float* a_s = shA + buf * (32 * 32);
        const float* b_s = shB + buf * (32 * 68);
        #pragma unroll
        for (int k = 0; k < 32; ++k) {
            const float a0 = a_s[(tm + 0) * 32 + k];
            const float a1 = a_s[(tm + 1) * 32 + k];
            const float a2 = a_s[(tm + 2) * 32 + k];
            const float a3 = a_s[(tm + 3) * 32 + k];
            const float4 b4 = *(const float4*)&b_s[k * 68 + tn];
            acc[0][0] = fmaf(a0, b4.x, acc[0][0]); acc[0][1] = fmaf(a0, b4.y, acc[0][1]);
            acc[0][2] = fmaf(a0, b4.z, acc[0][2]); acc[0][3] = fmaf(a0, b4.w, acc[0][3]);
            acc[1][0] = fmaf(a1, b4.x, acc[1][0]); acc[1][1] = fmaf(a1, b4.y, acc[1][1]);
            acc[1][2] = fmaf(a1, b4.z, acc[1][2]); acc[1][3] = fmaf(a1, b4.w, acc[1][3]);
            acc[2][0] = fmaf(a2, b4.x, acc[2][0]); acc[2][1] = fmaf(a2, b4.y, acc[2][1]);
            acc[2][2] = fmaf(a2, b4.z, acc[2][2]); acc[2][3] = fmaf(a2, b4.w, acc[2][3]);
            acc[3][0] = fmaf(a3, b4.x, acc[3][0]); acc[3][1] = fmaf(a3, b4.y, acc[3][1]);
            acc[3][2] = fmaf(a3, b4.z, acc[3][2]); acc[3][3] = fmaf(a3, b4.w, acc[3][3]);
        }
        if (c + 1 < nk) {
            float* a_d = shA + (buf ^ 1) * (32 * 32);
            float* b_d = shB + (buf ^ 1) * (32 * 68);
            *(float4*)&a_d[rA * 32 + sA]     = pa0;
            *(float4*)&a_d[rA * 32 + sA + 4] = pa1;
            b_d[(cB + 0) * 68 + rB] = pb0.x; b_d[(cB + 1) * 68 + rB] = pb0.y;
            b_d[(cB + 2) * 68 + rB] = pb0.z; b_d[(cB + 3) * 68 + rB] = pb0.w;
            b_d[(cB + 0) * 68 + rB + 16] = pb1.x; b_d[(cB + 1) * 68 + rB + 16] = pb1.y;
            b_d[(cB + 2) * 68 + rB + 16] = pb1.z; b_d[(cB + 3) * 68 + rB + 16] = pb1.w;
            b_d[(cB + 0) * 68 + rB + 32] = pb2.x; b_d[(cB + 1) * 68 + rB + 32] = pb2.y;
            b_d[(cB + 2) * 68 + rB + 32] = pb2.z; b_d[(cB + 3) * 68 + rB + 32] = pb2.w;
            b_d[(cB + 0) * 68 + rB + 48] = pb3.x; b_d[(cB + 1) * 68 + rB + 48] = pb3.y;
            b_d[(cB + 2) * 68 + rB + 48] = pb3.z; b_d[(cB + 3) * 68 + rB + 48] = pb3.w;
            __syncthreads();
        }
        buf ^= 1;
    }

    #pragma unroll
    for (int i = 0; i < 4; i++) {
        const int m = m0 + tm + i;
        float4 cv;
        cv.x = acc[i][0]; cv.y = acc[i][1]; cv.z = acc[i][2]; cv.w = acc[i][3];
        if (bias) {
            cv.x += bias[n0 + tn + 0]; cv.y += bias[n0 + tn + 1];
            cv.z += bias[n0 + tn + 2]; cv.w += bias[n0 + tn + 3];
        }
        *(float4*)&C[(size_t)m * Ncols + n0 + tn] = cv;
    }
}

// gh for BOTH layers: gh = hidden[l] @ Whh[l]^T + bhh[l]  — grid (24,4,2)
__global__ __launch_bounds__(128) void gh_kernel(
    const float* __restrict__ hidden, const float* __restrict__ gwhh,
    const float* __restrict__ gbhh)
{
    __shared__ float shA[2 * 32 * 32];
    __shared__ float shB[2 * 32 * 68];
    const int layer = blockIdx.z;
    gemm_db(hidden + (size_t)layer * BB * HH,
            gwhh + (size_t)layer * 3 * HH * HH,
            g_gh + (size_t)layer * BB * 3 * HH,
            3 * HH, blockIdx.y * 32, blockIdx.x * 64, 0, HH,
            gbhh + layer * 3 * HH, shA, shB);
}

// gx split-K: partial[z] = x @ Wih[l]^T over K half z — grid (24,4,2)
__global__ __launch_bounds__(128) void gx_kernel(
    int layer, const float* __restrict__ gwih)
{
    __shared__ float shA[2 * 32 * 32];
    __shared__ float shB[2 * 32 * 68];
    const int kh = blockIdx.z;
    const float* x = layer ? g_x1 : g_x0;
    gemm_db(x, gwih + (size_t)layer * 3 * HH * HH,
            g_gxp + (size_t)kh * BB * 3 * HH,
            3 * HH, blockIdx.y * 32, blockIdx.x * 64, kh * 256, 256,
            nullptr, shA, shB);
}

// comb split-K=4: partial[z] = attn_applied @ wpacked^T over K quarter — grid (8,4,4)
__global__ __launch_bounds__(128) void comb_kernel()
{
    __shared__ float shA[2 * 32 * 32];
    __shared__ float shB[2 * 32 * 68];
    const int kq = blockIdx.z;
    gemm_db(g_attn_applied, g_wpacked,
            g_combp + (size_t)kq * BB * HH,
            HH, blockIdx.y * 32, blockIdx.x * 64, kq * 128, 128,
            nullptr, shA, shB);
}

// repack comb_w[:,1:513] -> contiguous 512x512
__global__ void repack_kernel(const float* __restrict__ comb_w) {
    const int i = blockIdx.x * blockDim.x + threadIdx.x;
    if (i < HH * HH) {
        const int h = i >> 9, j = i & 511;
        g_wpacked[i] = comb_w[h * 513 + 1 + j];
    }
}

// x0 = relu(sum of comb partials + comb_b + input0 * comb_w[:,0])
__global__ void comb_combine_kernel(const float* __restrict__ input,
                                    const float* __restrict__ comb_w,
                                    const float* __restrict__ comb_b)
{
    const int i = blockIdx.x * blockDim.x + threadIdx.x;
    if (i >= BB * HH) return;
    const int b = i >> 9, n = i & 511;
    float v = g_combp[i] + g_combp[BB * HH + i]
            + g_combp[2 * BB * HH + i] + g_combp[3 * BB * HH + i]
            + comb_b[n] + input[b * 8 + 7] * comb_w[n * 513];
    g_x0[i] = fmaxf(v, 0.f);
}

// GRU gates (sums gx partials + bih): h_new = (1-z)*n + z*h_prev
__global__ void gate_kernel(int layer, const float* __restrict__ hprev,
                            const float* __restrict__ gbih,
                            float* __restrict__ hout)
{
    const int i = blockIdx.x * blockDim.x + threadIdx.x;
    if (i >= BB * HH) return;
    const int b = i >> 9, h = i & 511;
    const float* gh  = g_gh + (size_t)layer * BB * 3 * HH + (size_t)b * 3 * HH;
    const float* p0  = g_gxp + (size_t)b * 3 * HH;
    const float* p1  = g_gxp + (size_t)BB * 3 * HH + (size_t)b * 3 * HH;
    const float xr = p0[h]        + p1[h]        + gbih[h];
    const float xz = p0[h + 512]  + p1[h + 512]  + gbih[h + 512];
    const float xn = p0[h + 1024] + p1[h + 1024] + gbih[h + 1024];
    const float r = 1.f / (1.f + __expf(-(xr + gh[h])));
    const float z = 1.f / (1.f + __expf(-(xz + gh[h + 512])));
    const float n = tanhf(xn + r * gh[h + 1024]);
    const float hp = hprev[i];
    const float hn = (1.f - z) * n + z * hp;
    hout[i] = hn;
    (layer ? g_x2 : g_x1)[i] = hn;
}

// output GEMV
__global__ void out_kernel(const float* __restrict__ out_w,
                           const float* __restrict__ out_b,
                           float* __restrict__ out)
{
    const int b = blockIdx.x;
    const int tid = threadIdx.x;   // 128
    float s = 0.f;
    #pragma unroll
    for (int j = tid; j < HH; j += 128) s = fmaf(g_x2[b * HH + j], out_w[j], s);
    #pragma unroll
    for (int o = 16; o > 0; o >>= 1) s += __shfl_xor_sync(0xffffffffu, s, o);
    __shared__ float red[4];
    if ((tid & 31) == 0) red[tid >> 5] = s;
    __syncthreads();
    if (tid == 0) out[b] = red[0] + red[1] + red[2] + red[3] + out_b[0];
}

// =====================================================================
extern "C" void kernel_launch(void* const* d_in, const int* in_sizes, int n_in,
                              void* d_out, int out_size)
{
    const float* input   = (const float*)d_in[0];
    const float* hidden  = (const float*)d_in[1];
    const float* enc     = (const float*)d_in[2];
    const float* attn_w  = (const float*)d_in[3];
    const float* attn_b  = (const float*)d_in[4];
    const float* comb_w  = (const float*)d_in[5];
    const float* comb_b  = (const float*)d_in[6];
    const float* gwih    = (const float*)d_in[7];
    const float* gwhh    = (const float*)d_in[8];
    const float* gbih    = (const float*)d_in[9];
    const float* gbhh    = (const float*)d_in[10];
    const float* out_w   = (const float*)d_in[11];
    const float* out_b   = (const float*)d_in[12];

    float* out        = (float*)d_out;
    float* out_hidden = out + BB;
    float* out_attnw  = out + BB + LL * BB * HH;

    repack_kernel<<<512, 512>>>(comb_w);
    gh_kernel<<<dim3(24, 4, 2), 128>>>(hidden, gwhh, gbhh);       // independent of chain
    attn_kernel<<<BB, 512>>>(hidden, enc, attn_w, attn_b, out_attnw);

    comb_kernel<<<dim3(8, 4, 4), 128>>>();
    comb_combine_kernel<<<256, 256>>>(input, comb_w, comb_b);

    gx_kernel<<<dim3(24, 4, 2), 128>>>(0, gwih);
    gate_kernel<<<256, 256>>>(0, hidden, gbih, out_hidden);

    gx_kernel<<<dim3(24, 4, 2), 128>>>(1, gwih);
    gate_kernel<<<256, 256>>>(1, hidden + BB * HH, gbih + 3 * HH, out_hidden + BB * HH);

    out_kernel<<<BB, 128>>>(out_w, out_b, out);
}